// round 10
// baseline (speedup 1.0000x reference)
#include <cuda_runtime.h>
#include <cuda_bf16.h>

#define BATCH 4
#define NP    8192
#define NQ    2048
#define CF    64
#define CT    64
#define KS    32
#define R2    0.04f
#define OUTC  (3 + CF)        // 67 channels in grouped_features

__device__ int g_idx[BATCH * NQ * KS];      // ball-query result (padded)

// Ball query: whole batch cloud resident in 96KB dynamic smem (SoA), loaded
// directly from [B,Np,3]. 1024 threads, one query per warp (32 q/block),
// per-warp early exit. Writes g_idx + the 3 centered coord channels.
__global__ __launch_bounds__(1024) void qg_ballquery_kernel(
    const float* __restrict__ coords,
    const float* __restrict__ queries,
    float* __restrict__ out)
{
    extern __shared__ float sxyz[];                  // sx[NP] | sy[NP] | sz[NP]
    float* sx = sxyz;
    __shared__ int slots_s[32][KS];

    int tid  = threadIdx.x;
    int lane = tid & 31;
    int w    = tid >> 5;
    int b    = blockIdx.x >> 6;                      // 64 blocks per batch
    int blk  = blockIdx.x & 63;

    // Load whole cloud once: coalesced reads of the flat [Np*3] array -> SoA smem.
    const float* cb = coords + (size_t)b * NP * 3;
    #pragma unroll
    for (int j = 0; j < (NP * 3) / 1024; ++j) {
        int i = tid + j * 1024;
        float v = cb[i];
        int p = i / 3, d = i - 3 * p;
        sxyz[d * NP + p] = v;
    }
    __syncthreads();

    float* sy = sxyz + NP;
    float* sz = sxyz + 2 * NP;
    int* slots = slots_s[w];
    unsigned lt = (1u << lane) - 1u;
    const size_t stride = (size_t)NQ * KS;

    int q = blk * 32 + w;
    int g = b * NQ + q;
    const float* qp = queries + (size_t)g * 3;
    float qx = qp[0], qy = qp[1], qz = qp[2];

    int count = 0;
    for (int base = 0; base < NP; base += 64) {
        int i0 = base + lane, i1 = base + 32 + lane;
        float x0 = sx[i0], y0 = sy[i0], z0 = sz[i0];
        float x1 = sx[i1], y1 = sy[i1], z1 = sz[i1];
        // Match XLA rounding exactly: no FMA contraction.
        float dx0 = __fadd_rn(qx, -x0), dy0 = __fadd_rn(qy, -y0), dz0 = __fadd_rn(qz, -z0);
        float d20 = __fadd_rn(__fadd_rn(__fmul_rn(dx0, dx0), __fmul_rn(dy0, dy0)),
                              __fmul_rn(dz0, dz0));
        float dx1 = __fadd_rn(qx, -x1), dy1 = __fadd_rn(qy, -y1), dz1 = __fadd_rn(qz, -z1);
        float d21 = __fadd_rn(__fadd_rn(__fmul_rn(dx1, dx1), __fmul_rn(dy1, dy1)),
                              __fmul_rn(dz1, dz1));
        bool in0 = d20 < R2;
        bool in1 = d21 < R2;
        unsigned m0 = __ballot_sync(0xffffffffu, in0);
        unsigned m1 = __ballot_sync(0xffffffffu, in1);
        if (in0) {
            int s = count + __popc(m0 & lt);
            if (s < KS) slots[s] = i0;
        }
        int c1 = count + __popc(m0);
        if (in1) {
            int s = c1 + __popc(m1 & lt);
            if (s < KS) slots[s] = i1;
        }
        count = c1 + __popc(m1);
        if (count >= KS) break;
    }
    __syncwarp();

    int cnt   = count < KS ? count : KS;
    int first = (count > 0) ? slots[0] : 0;
    int my    = (lane < cnt) ? slots[lane] : first;
    g_idx[(size_t)g * KS + lane] = my;

    // coord channels 0..2 (centered)
    size_t ob0 = (size_t)b * OUTC * stride + (size_t)q * KS + lane;
    out[ob0]              = sx[my] - qx;
    out[ob0 + stride]     = sy[my] - qy;
    out[ob0 + 2 * stride] = sz[my] - qz;
}

// Gather: one block per (batch, PAIR of channel planes). 256 blocks, 64KB dyn smem.
// Each idx4 load feeds lookups/stores for BOTH planes (idx traffic halved, ILP 2x).
__global__ __launch_bounds__(256) void qg_gather_kernel(
    const float* __restrict__ feats,
    const float* __restrict__ temb,
    float* __restrict__ out)
{
    extern __shared__ float rows[];     // r0[NP] | r1[NP]  (64KB)
    float* r0 = rows;
    float* r1 = rows + NP;

    int tid = threadIdx.x;
    int bc  = blockIdx.x;               // 0..255
    int b   = bc >> 6;
    int cc  = (bc & 63) * 2;            // even channel in 0..126
    int which = cc >> 6;                // 0: feats, 1: temb (pair never straddles)
    int ch  = cc & 63;

    const float* s0 = (which ? temb : feats) + ((size_t)b * 64 + ch) * NP;
    // Load both channel rows (coalesced float4): 2*NP floats.
    #pragma unroll
    for (int j = 0; j < NP / (256 * 4); ++j) {
        int e = (tid + j * 256) * 4;
        *(float4*)(&r0[e]) = *(const float4*)(s0 + e);
        *(float4*)(&r1[e]) = *(const float4*)(s0 + NP + e);
    }
    __syncthreads();

    const size_t stride = (size_t)NQ * KS;
    size_t ob0, ob1;
    if (which == 0) {
        ob0 = (size_t)b * OUTC * stride + (size_t)(3 + ch) * stride;
        ob1 = ob0 + stride;
    } else {
        ob0 = (size_t)BATCH * OUTC * stride + (size_t)b * CT * stride + (size_t)ch * stride;
        ob1 = ob0 + stride;
    }

    const int4* idx4 = (const int4*)(g_idx + (size_t)b * NQ * KS);

    // 16K int4 groups; 256 threads -> 64 iterations; each idx feeds 2 planes.
    #pragma unroll 4
    for (int it = 0; it < (NQ * KS / 4) / 256; ++it) {
        int e = it * 256 + tid;
        int4 iv = idx4[e];
        float4 v0 = make_float4(r0[iv.x], r0[iv.y], r0[iv.z], r0[iv.w]);
        float4 v1 = make_float4(r1[iv.x], r1[iv.y], r1[iv.z], r1[iv.w]);
        *(float4*)(out + ob0 + (size_t)e * 4) = v0;
        *(float4*)(out + ob1 + (size_t)e * 4) = v1;
    }
}

extern "C" void kernel_launch(void* const* d_in, const int* in_sizes, int n_in,
                              void* d_out, int out_size) {
    const float* coords  = (const float*)d_in[0];  // [B,Np,3]
    const float* feats   = (const float*)d_in[1];  // [B,C,Np]
    const float* temb    = (const float*)d_in[2];  // [B,Ct,Np]
    const float* queries = (const float*)d_in[3];  // [B,Nq,3]
    float* out = (float*)d_out;

    const int bq_smem = 3 * NP * (int)sizeof(float);   // 96KB
    const int gt_smem = 2 * NP * (int)sizeof(float);   // 64KB
    cudaFuncSetAttribute(qg_ballquery_kernel,
                         cudaFuncAttributeMaxDynamicSharedMemorySize, bq_smem);
    cudaFuncSetAttribute(qg_gather_kernel,
                         cudaFuncAttributeMaxDynamicSharedMemorySize, gt_smem);

    qg_ballquery_kernel<<<BATCH * 64, 1024, bq_smem>>>(coords, queries, out);
    qg_gather_kernel<<<BATCH * 64, 256, gt_smem>>>(feats, temb, out);
}

// round 11
// speedup vs baseline: 1.0717x; 1.0717x over previous
#include <cuda_runtime.h>
#include <cuda_bf16.h>

#define BATCH 4
#define NP    8192
#define NQ    2048
#define CF    64
#define CT    64
#define KS    32
#define R2    0.04f
#define OUTC  (3 + CF)        // 67 channels in grouped_features

__device__ int g_idx[BATCH * NQ * KS];      // ball-query result (padded)

// Ball query: whole batch cloud in 96KB dynamic smem (SoA). 1024 threads, one
// query per warp; 128 points per iteration (4 ballot groups) for short chains.
__global__ __launch_bounds__(1024) void qg_ballquery_kernel(
    const float* __restrict__ coords,
    const float* __restrict__ queries,
    float* __restrict__ out)
{
    extern __shared__ float sxyz[];                  // sx[NP] | sy[NP] | sz[NP]
    float* sx = sxyz;
    __shared__ int slots_s[32][KS];

    int tid  = threadIdx.x;
    int lane = tid & 31;
    int w    = tid >> 5;
    int b    = blockIdx.x >> 6;                      // 64 blocks per batch
    int blk  = blockIdx.x & 63;

    const float* cb = coords + (size_t)b * NP * 3;
    #pragma unroll
    for (int j = 0; j < (NP * 3) / 1024; ++j) {
        int i = tid + j * 1024;
        float v = cb[i];
        int p = i / 3, d = i - 3 * p;
        sxyz[d * NP + p] = v;
    }
    __syncthreads();

    float* sy = sxyz + NP;
    float* sz = sxyz + 2 * NP;
    int* slots = slots_s[w];
    unsigned lt = (1u << lane) - 1u;
    const size_t stride = (size_t)NQ * KS;

    int q = blk * 32 + w;
    int g = b * NQ + q;
    const float* qp = queries + (size_t)g * 3;
    float qx = qp[0], qy = qp[1], qz = qp[2];

    int count = 0;
    for (int base = 0; base < NP; base += 128) {
        unsigned m[4];
        bool in[4];
        #pragma unroll
        for (int u = 0; u < 4; ++u) {
            int i = base + u * 32 + lane;
            float x = sx[i], y = sy[i], z = sz[i];
            // Match XLA rounding exactly: no FMA contraction.
            float dx = __fadd_rn(qx, -x), dy = __fadd_rn(qy, -y), dz = __fadd_rn(qz, -z);
            float d2 = __fadd_rn(__fadd_rn(__fmul_rn(dx, dx), __fmul_rn(dy, dy)),
                                 __fmul_rn(dz, dz));
            in[u] = d2 < R2;
            m[u]  = __ballot_sync(0xffffffffu, in[u]);
        }
        #pragma unroll
        for (int u = 0; u < 4; ++u) {
            if (in[u]) {
                int s = count + __popc(m[u] & lt);
                if (s < KS) slots[s] = base + u * 32 + lane;
            }
            count += __popc(m[u]);
        }
        if (count >= KS) break;
    }
    __syncwarp();

    int cnt   = count < KS ? count : KS;
    int first = (count > 0) ? slots[0] : 0;
    int my    = (lane < cnt) ? slots[lane] : first;
    g_idx[(size_t)g * KS + lane] = my;

    size_t ob0 = (size_t)b * OUTC * stride + (size_t)q * KS + lane;
    out[ob0]              = sx[my] - qx;
    out[ob0 + stride]     = sy[my] - qy;
    out[ob0 + 2 * stride] = sz[my] - qz;
}

// Gather: block per (batch, channel-pair, query-chunk) = 512 blocks.
// Two channel rows interleaved as float2 in smem (LDS.64 -> both channels).
// Prefetched idx4, 2 independent groups per iteration (>=4 outstanding LDGs).
__global__ __launch_bounds__(256) void qg_gather_kernel(
    const float* __restrict__ feats,
    const float* __restrict__ temb,
    float* __restrict__ out)
{
    extern __shared__ float2 rows[];    // [NP] interleaved pair (64KB)

    int tid   = threadIdx.x;
    int bc    = blockIdx.x;             // 0..511
    int chunk = bc & 1;
    int pair  = (bc >> 1) & 63;
    int b     = bc >> 7;
    int cc    = pair * 2;               // 0..126
    int which = cc >> 6;
    int ch    = cc & 63;

    const float* s0 = (which ? temb : feats) + ((size_t)b * 64 + ch) * NP;
    for (int p = tid; p < NP; p += 256)
        rows[p] = make_float2(s0[p], s0[NP + p]);    // coalesced LDG.32 x2, STS.64
    __syncthreads();

    const size_t stride = (size_t)NQ * KS;
    size_t ob0;
    if (which == 0)
        ob0 = (size_t)b * OUTC * stride + (size_t)(3 + ch) * stride;
    else
        ob0 = (size_t)BATCH * OUTC * stride + (size_t)b * CT * stride + (size_t)ch * stride;
    size_t ob1 = ob0 + stride;

    const int4* idx4 = (const int4*)(g_idx + (size_t)b * NQ * KS);
    int g0 = chunk * (NQ * KS / 8);     // 8192 int4 groups per chunk
    // Two independent streams: groups [g0 .. g0+4096) and [g0+4096 .. g0+8192)
    int eA = g0 + tid;
    int eB = g0 + 4096 + tid;
    int4 A = idx4[eA];
    int4 B = idx4[eB];

    #pragma unroll 4
    for (int it = 0; it < 16; ++it) {
        int4 nA, nB;
        if (it < 15) {
            nA = idx4[eA + (it + 1) * 256];
            nB = idx4[eB + (it + 1) * 256];
        }
        float2 a0 = rows[A.x], a1 = rows[A.y], a2 = rows[A.z], a3 = rows[A.w];
        float2 b0 = rows[B.x], b1 = rows[B.y], b2 = rows[B.z], b3 = rows[B.w];
        size_t pa = (size_t)(eA + it * 256 - g0 + chunk * 8192) * 4;
        size_t pb = (size_t)(eB + it * 256 - g0 + chunk * 8192) * 4;
        *(float4*)(out + ob0 + pa) = make_float4(a0.x, a1.x, a2.x, a3.x);
        *(float4*)(out + ob1 + pa) = make_float4(a0.y, a1.y, a2.y, a3.y);
        *(float4*)(out + ob0 + pb) = make_float4(b0.x, b1.x, b2.x, b3.x);
        *(float4*)(out + ob1 + pb) = make_float4(b0.y, b1.y, b2.y, b3.y);
        A = nA; B = nB;
    }
}

extern "C" void kernel_launch(void* const* d_in, const int* in_sizes, int n_in,
                              void* d_out, int out_size) {
    const float* coords  = (const float*)d_in[0];  // [B,Np,3]
    const float* feats   = (const float*)d_in[1];  // [B,C,Np]
    const float* temb    = (const float*)d_in[2];  // [B,Ct,Np]
    const float* queries = (const float*)d_in[3];  // [B,Nq,3]
    float* out = (float*)d_out;

    const int bq_smem = 3 * NP * (int)sizeof(float);    // 96KB
    const int gt_smem = NP * (int)sizeof(float2);       // 64KB
    cudaFuncSetAttribute(qg_ballquery_kernel,
                         cudaFuncAttributeMaxDynamicSharedMemorySize, bq_smem);
    cudaFuncSetAttribute(qg_gather_kernel,
                         cudaFuncAttributeMaxDynamicSharedMemorySize, gt_smem);

    qg_ballquery_kernel<<<BATCH * 64, 1024, bq_smem>>>(coords, queries, out);
    qg_gather_kernel<<<BATCH * 128, 256, gt_smem>>>(feats, temb, out);
}